// round 7
// baseline (speedup 1.0000x reference)
#include <cuda_runtime.h>
#include <math.h>

#define B_ 64
#define T_ 2048
#define I_ 64
#define S_ 128
#define O_ 64
#define LN_EPS 1e-5f
#define NSEG 8
#define SEGT 256
#define TP 2052
#define NWORK 84
#define NGATE 512
#define DSMEM 118784

typedef unsigned long long ull;

__device__ float g_GX[2ull*B_*TP*S_];
__device__ float g_H [B_*T_*S_];
__device__ float g_xsum[B_*I_];
__device__ float g_boSum[B_*O_];
__device__ float g_boSsq[B_*O_];
__device__ float g_S1, g_S2, g_SA;
__device__ int g_ctr;
__device__ int g_gdone[NGATE];
__device__ int g_rprog[B_];

__device__ __forceinline__ ull pack2(float lo, float hi) {
    ull r; asm("mov.b64 %0,{%1,%2};" : "=l"(r) : "f"(lo), "f"(hi)); return r;
}
__device__ __forceinline__ void unpack2(ull v, float &lo, float &hi) {
    asm("mov.b64 {%0,%1},%2;" : "=f"(lo), "=f"(hi) : "l"(v));
}
__device__ __forceinline__ ull ffma2(ull a, ull b, ull c) {
    ull d; asm("fma.rn.f32x2 %0,%1,%2,%3;" : "=l"(d) : "l"(a), "l"(b), "l"(c)); return d;
}

__global__ void zeroK() {
    int i = blockIdx.x * blockDim.x + threadIdx.x;
    if (i < B_*O_) { g_boSum[i] = 0.f; g_boSsq[i] = 0.f; }
    if (i < B_*I_) g_xsum[i] = 0.f;
    if (i < NGATE) g_gdone[i] = 0;
    if (i < B_)    g_rprog[i] = 0;
    if (i == 0) { g_S1 = 0.f; g_S2 = 0.f; g_SA = 0.f; g_ctr = 0; }
}

// ---------------- gate tile: (b, seg) -> gates + x@B^T + x colsums ----------------
__device__ void gate_task(int task, char* sm,
    const float* __restrict__ x, const float* __restrict__ Wsel,
    const float* __restrict__ bsel, const float* __restrict__ Bm)
{
    int seg = task >> 6, b = task & 63;
    float* xs  = (float*)sm;        // [4][64]
    float* ysm = xs + 256;          // [4][256]
    int tid = threadIdx.x;
    bool isG = tid < S_;
    int s = isG ? tid : tid - S_;
    const float* wrow = isG ? (Wsel + s*I_) : (Bm + s*I_);
    ull w2[I_/2];
#pragma unroll
    for (int k = 0; k < I_/2; k++) w2[k] = pack2(wrow[2*k], wrow[2*k+1]);
    float bias = isG ? bsel[s] : 0.f;

    int t0 = seg * SEGT;
    const float* xrow = x + ((size_t)b*T_ + t0)*I_;
    float2* outp = ((float2*)g_GX) + (size_t)b*TP*S_;
    float xacc = 0.f;

    for (int g = 0; g < SEGT; g += 4) {
        { int r = tid >> 6, i = tid & 63;
          xs[r*64 + i] = xrow[(g + r)*I_ + i]; }
        __syncthreads();
#pragma unroll
        for (int r = 0; r < 4; r++) {
            const ull* xv = (const ull*)(xs + r*64);
            ull a0 = 0, a1 = 0, a2 = 0, a3 = 0;
#pragma unroll
            for (int k = 0; k < I_/2; k += 4) {
                a0 = ffma2(w2[k+0], xv[k+0], a0);
                a1 = ffma2(w2[k+1], xv[k+1], a1);
                a2 = ffma2(w2[k+2], xv[k+2], a2);
                a3 = ffma2(w2[k+3], xv[k+3], a3);
            }
            float p,qf,u,v,e,f,m,n;
            unpack2(a0,p,qf); unpack2(a1,u,v); unpack2(a2,e,f); unpack2(a3,m,n);
            float dot = ((p+qf)+(u+v)) + ((e+f)+(m+n));
            if (isG) ysm[r*256 + 2*s]     = 1.f / (1.f + __expf(-(dot + bias)));
            else     ysm[r*256 + 2*s + 1] = dot;
        }
        if (tid < 64) xacc += (xs[tid]+xs[64+tid]) + (xs[128+tid]+xs[192+tid]);
        __syncthreads();
        const float2* fy = (const float2*)ysm;
#pragma unroll
        for (int rr = 0; rr < 2; rr++) {
            int idx = tid + rr*256;
            outp[(size_t)(t0 + g + (idx >> 7))*S_ + (idx & 127)] = fy[idx];
        }
        __syncthreads();
    }
    if (tid < 64) atomicAdd(&g_xsum[b*64 + tid], xacc);
    __threadfence();
    __syncthreads();
    if (tid == 0) atomicExch(&g_gdone[(b << 3) + seg], 1);
}

// ---------------- out tile: (b, seg) -> Y, final row, stats ----------------
__device__ void out_task(int task, char* sm,
    const float* __restrict__ x, const float* __restrict__ C,
    const float* __restrict__ D, float* __restrict__ out)
{
    int seg = task >> 6, b = task & 63;
    // wait for recurrence progress
    if (threadIdx.x == 0) {
        int need = (seg + 1) << 8;
        while (atomicAdd(&g_rprog[b], 0) < need) {}
        __threadfence();
    }
    __syncthreads();

    ull*   Cp = (ull*)sm;           // [64][64]
    ull*   Dp = Cp + 4096;          // [32][64]
    float* Hs = (float*)(Dp + 2048);
    float* xs = Hs + 512;
    float* Ys = xs + 256;
    float* yp = Ys + 256;

    int tid = threadIdx.x;
    int tl = tid >> 6, o = tid & 63;
    int t0 = seg * SEGT;

    for (int idx = tid; idx < 64*64; idx += 256) {
        int k = idx >> 6, oo = idx & 63;
        Cp[idx] = pack2(C[oo*S_ + 2*k], C[oo*S_ + 2*k + 1]);
    }
    for (int idx = tid; idx < 32*64; idx += 256) {
        int k = idx >> 6, oo = idx & 63;
        Dp[idx] = pack2(D[oo*I_ + 2*k], D[oo*I_ + 2*k + 1]);
    }
    if (tid < 64) yp[tid] = 0.f;
    __syncthreads();

    if (seg > 0) {
        if (tid < 128) Hs[tid] = g_H[((size_t)b*T_ + (t0-1))*S_ + tid];
        if (tid >= 128 && tid < 192) xs[tid-128] = x[((size_t)b*T_ + (t0-1))*I_ + (tid-128)];
        __syncthreads();
        if (tid < 64) {
            const ull* hv = (const ull*)Hs;
            ull ac0 = 0, ac1 = 0;
#pragma unroll
            for (int k = 0; k < 64; k += 2) {
                ac0 = ffma2(hv[k],   Cp[k*64 + tid],     ac0);
                ac1 = ffma2(hv[k+1], Cp[(k+1)*64 + tid], ac1);
            }
            const ull* xv = (const ull*)xs;
#pragma unroll
            for (int k = 0; k < 32; k += 2) {
                ac0 = ffma2(xv[k],   Dp[k*64 + tid],     ac0);
                ac1 = ffma2(xv[k+1], Dp[(k+1)*64 + tid], ac1);
            }
            float u,v,e,f; unpack2(ac0,u,v); unpack2(ac1,e,f);
            yp[tid] = (u+v)+(e+f);
        }
    }
    __syncthreads();

    float boS = 0.f, boQ = 0.f;
    float nrmAcc = 0.f, difAcc = 0.f;
    int w = tid >> 5, lane = tid & 31;

    for (int g = 0; g < SEGT/4; g++) {
        int tbase = t0 + g*4;
        Hs[tid]       = g_H[((size_t)b*T_ + tbase + (tid >> 7))    *S_ + (tid & 127)];
        Hs[tid + 256] = g_H[((size_t)b*T_ + tbase + 2 + (tid >> 7))*S_ + (tid & 127)];
        xs[tid]       = x  [((size_t)b*T_ + tbase + (tid >> 6))    *I_ + (tid & 63)];
        __syncthreads();

        float y;
        {
            const ull* hv = (const ull*)(Hs + tl*128);
            ull ac0 = 0, ac1 = 0;
#pragma unroll
            for (int k = 0; k < 64; k += 2) {
                ac0 = ffma2(hv[k],   Cp[k*64 + o],     ac0);
                ac1 = ffma2(hv[k+1], Cp[(k+1)*64 + o], ac1);
            }
            const ull* xv = (const ull*)(xs + tl*64);
#pragma unroll
            for (int k = 0; k < 32; k += 2) {
                ac0 = ffma2(xv[k],   Dp[k*64 + o],     ac0);
                ac1 = ffma2(xv[k+1], Dp[(k+1)*64 + o], ac1);
            }
            float u,v,e,f; unpack2(ac0,u,v); unpack2(ac1,e,f);
            y = (u+v)+(e+f);
        }
        Ys[tl*64 + o] = y;
        boS += y; boQ += y*y;
        if (tbase + tl == T_ - 1) out[b*O_ + o] = y;
        __syncthreads();

        if (w < 4) {
            float y0 = Ys[w*64 + lane], y1 = Ys[w*64 + lane + 32];
            float p0, p1;
            if (w == 0) { p0 = yp[lane]; p1 = yp[lane + 32]; }
            else        { p0 = Ys[(w-1)*64 + lane]; p1 = Ys[(w-1)*64 + lane + 32]; }
            float sn = y0*y0 + y1*y1;
            float d0 = y0 - p0, d1 = y1 - p1;
            float dn = d0*d0 + d1*d1;
#pragma unroll
            for (int off = 16; off > 0; off >>= 1) {
                sn += __shfl_xor_sync(0xffffffffu, sn, off);
                dn += __shfl_xor_sync(0xffffffffu, dn, off);
            }
            if (lane == 0) {
                nrmAcc += sqrtf(sn);
                if (tbase + w > 0) difAcc += sqrtf(dn);
            }
        }
        __syncthreads();
        if (tid < 64) yp[tid] = Ys[3*64 + tid];
        __syncthreads();
    }

    if (w < 4 && lane == 0) {
        atomicAdd(&g_S2, nrmAcc);
        atomicAdd(&g_S1, difAcc);
    }
    __syncthreads();
    Ys[tid] = boS;
    __syncthreads();
    if (tl == 0) atomicAdd(&g_boSum[b*64 + o], (Ys[o] + Ys[64+o]) + (Ys[128+o] + Ys[192+o]));
    __syncthreads();
    Ys[tid] = boQ;
    __syncthreads();
    if (tl == 0) atomicAdd(&g_boSsq[b*64 + o], (Ys[o] + Ys[64+o]) + (Ys[128+o] + Ys[192+o]));
    __syncthreads();
}

// ---------------- recurrence (CTA = one batch) ----------------
__device__ void rec_run(char* sm, const float* __restrict__ A,
    const float* __restrict__ gamma, const float* __restrict__ beta)
{
    float (*hbuf)[136] = (float (*)[136])sm;           // 2 x 136
    float2 (*red)[8]   = (float2 (*)[8])(sm + 1088);   // 2 x 8
    int tid = threadIdx.x, b = blockIdx.x;
    int w = tid >> 5, lane = tid & 31;
    int s = (w << 4) + (lane >> 1);
    int q = lane & 1;
    int hoff = s + ((s & 64) >> 4);
    const float invS = 1.f/(float)S_;

    float gam_s = gamma[s], bet_s = beta[s];
    float gamI = gam_s * invS;
    float agI = 0.f, abv = 0.f;
    {
        const float* ar = A + s*S_;
#pragma unroll 16
        for (int k = 0; k < S_; k++) { agI += ar[k]*gamma[k]; abv += ar[k]*beta[k]; }
        agI *= invS;
    }
    ull a2[32];
    {
        const float* ar = A + s*S_ + q*64;
        const float* gm = gamma + q*64;
#pragma unroll
        for (int k = 0; k < 32; k++)
            a2[k] = pack2(ar[2*k]*gm[2*k], ar[2*k+1]*gm[2*k+1]);
    }

    if (tid < 136) { hbuf[0][tid] = 0.f; hbuf[1][tid] = 0.f; }
    if (tid < 16)  ((float2*)red)[tid] = make_float2(0.f, 0.f);

    // wait for gate seg 0
    if (tid == 0) {
        while (atomicAdd(&g_gdone[b << 3], 0) == 0) {}
        __threadfence();
    }
    __syncthreads();

    const float2* GX = ((const float2*)g_GX) + (size_t)b*TP*S_ + s;
    float* Hp = g_H + (size_t)b*T_*S_ + s;
    float2 gx[4];
#pragma unroll
    for (int j = 0; j < 4; j++) gx[j] = GX[(size_t)j*S_];
    float hbmine = 0.f;
    __syncthreads();

    int p = 0;
#pragma unroll 4
    for (int t = 0; t < T_; t++) {
        int tn = t + 4;
        if (tn < T_ && (tn & 255) == 0) {
            if (tid == 0) {
                while (atomicAdd(&g_gdone[(b << 3) + (tn >> 8)], 0) == 0) {}
                __threadfence();
            }
            __syncthreads();
        }
        float2 gxv = gx[t & 3];
        gx[t & 3] = GX[(size_t)tn*S_];

        const float4* rp = (const float4*)red[p];
        float4 r0 = rp[0], r1 = rp[1], r2 = rp[2], r3 = rp[3];
        float sum = ((r0.x + r0.z) + (r1.x + r1.z)) + ((r2.x + r2.z) + (r3.x + r3.z));
        float ssq = ((r0.y + r0.w) + (r1.y + r1.w)) + ((r2.y + r2.w) + (r3.y + r3.w));
        float mu  = sum * invS;
        float ve  = fmaf(ssq, invS, LN_EPS) - mu*mu;
        float rin = rsqrtf(ve);

        const ulonglong2* hv = (const ulonglong2*)(&hbuf[p][q*68]);
        ull ac0 = 0, ac1 = 0, ac2 = 0, ac3 = 0;
#pragma unroll
        for (int i = 0; i < 16; i += 4) {
            ulonglong2 pv = hv[i], rv = hv[i+1], uv = hv[i+2], vv = hv[i+3];
            ac0 = ffma2(a2[2*i+0], pv.x, ac0); ac1 = ffma2(a2[2*i+1], pv.y, ac1);
            ac2 = ffma2(a2[2*i+2], rv.x, ac2); ac3 = ffma2(a2[2*i+3], rv.y, ac3);
            ac0 = ffma2(a2[2*i+4], uv.x, ac0); ac1 = ffma2(a2[2*i+5], uv.y, ac1);
            ac2 = ffma2(a2[2*i+6], vv.x, ac2); ac3 = ffma2(a2[2*i+7], vv.y, ac3);
        }
        float p0,p1,p2,p3,p4,p5,p6,p7;
        unpack2(ac0,p0,p1); unpack2(ac1,p2,p3); unpack2(ac2,p4,p5); unpack2(ac3,p6,p7);
        float dmine = ((p0+p1)+(p2+p3)) + ((p4+p5)+(p6+p7));
        float dfull = dmine + __shfl_xor_sync(0xffffffffu, dmine, 1);

        float abx  = (t > 0) ? (abv + gxv.y) : gxv.y;
        float preh = hbmine * gam_s;
        float hpn = (t > 0) ? fmaf(fmaf(-sum, gamI, preh), rin, bet_s) : 0.f;
        float nextraw = fmaf(fmaf(-sum, agI, dfull), rin, abx);
        float hb = fmaf(gxv.x, nextraw - hpn, hpn);
        if (t > 0 && !q) Hp[(size_t)(t-1)*S_] = hpn;
        if (!q) hbuf[p ^ 1][hoff] = hb;
        hbmine = hb;

        float s1 = hb, s2 = hb*hb;
#pragma unroll
        for (int off = 16; off > 1; off >>= 1) {
            s1 += __shfl_xor_sync(0xffffffffu, s1, off);
            s2 += __shfl_xor_sync(0xffffffffu, s2, off);
        }
        if (lane == 0) red[p ^ 1][w] = make_float2(s1, s2);

        bool pub = ((t & 255) == 0) && (t != 0);
        if (pub) __threadfence();
        __syncthreads();
        if (pub && tid == 0) atomicExch(&g_rprog[b], t);
        p ^= 1;
    }

    // final normalize + store h_{T-1}, publish completion
    {
        const float4* rp = (const float4*)red[p];
        float4 r0 = rp[0], r1 = rp[1], r2 = rp[2], r3 = rp[3];
        float sum = ((r0.x + r0.z) + (r1.x + r1.z)) + ((r2.x + r2.z) + (r3.x + r3.z));
        float ssq = ((r0.y + r0.w) + (r1.y + r1.w)) + ((r2.y + r2.w) + (r3.y + r3.w));
        float mu  = sum * invS;
        float ve  = fmaf(ssq, invS, LN_EPS) - mu*mu;
        float rin = rsqrtf(ve);
        float hpn = fmaf(fmaf(-sum, gamI, hbmine*gam_s), rin, bet_s);
        if (!q) Hp[(size_t)(T_-1)*S_] = hpn;
    }
    __threadfence();
    __syncthreads();
    if (tid == 0) atomicExch(&g_rprog[b], T_);
}

// ---------------- persistent fused kernel ----------------
__global__ __launch_bounds__(256, 1) void megaK(
    const float* __restrict__ x, const float* __restrict__ Wsel,
    const float* __restrict__ bsel, const float* __restrict__ Bm,
    const float* __restrict__ A, const float* __restrict__ gamma,
    const float* __restrict__ beta, const float* __restrict__ C,
    const float* __restrict__ D, float* __restrict__ out)
{
    extern __shared__ __align__(16) char sm[];
    if (blockIdx.x < B_) {
        rec_run(sm, A, gamma, beta);
        return;
    }
    __shared__ int tsk;
    for (;;) {
        __syncthreads();
        if (threadIdx.x == 0) tsk = atomicAdd(&g_ctr, 1);
        __syncthreads();
        int task = tsk;
        if (task >= 2*NGATE) break;
        if (task < NGATE) gate_task(task, sm, x, Wsel, bsel, Bm);
        else              out_task(task - NGATE, sm, x, C, D, out);
    }
}

__global__ __launch_bounds__(128) void selFin(
    const float* __restrict__ Wsel, const float* __restrict__ bsel)
{
    __shared__ float part[4];
    int tid = threadIdx.x, b = blockIdx.x;
    float acc = bsel[tid];
    const float invT = 1.0f/(float)T_;
    const float* w  = Wsel + tid*I_;
    const float* xm = g_xsum + b*I_;
#pragma unroll 8
    for (int k = 0; k < I_; k++) acc += xm[k]*invT*w[k];
    float sg = 1.f/(1.f + __expf(-acc));
#pragma unroll
    for (int off = 16; off > 0; off >>= 1) sg += __shfl_xor_sync(0xffffffffu, sg, off);
    if ((tid & 31) == 0) part[tid >> 5] = sg;
    __syncthreads();
    if (tid == 0) atomicAdd(&g_SA, (part[0]+part[1]) + (part[2]+part[3]));
}

__global__ void finK(float* __restrict__ out)
{
    __shared__ float part[8];
    int tid = threadIdx.x;
    float acc = 0.f;
    for (int idx = tid; idx < B_*O_; idx += 256) {
        float sum = g_boSum[idx], ssq = g_boSsq[idx];
        float var = (ssq - sum*sum*(1.f/T_)) * (1.f/(T_ - 1));
        acc += sqrtf(fmaxf(var, 0.f));
    }
#pragma unroll
    for (int off = 16; off > 0; off >>= 1) acc += __shfl_xor_sync(0xffffffffu, acc, off);
    if ((tid & 31) == 0) part[tid >> 5] = acc;
    __syncthreads();
    if (tid == 0) {
        float tot = 0.f;
#pragma unroll
        for (int k = 0; k < 8; k++) tot += part[k];
        out[4096] = 1.f / (1.f + g_S1 / (float)(B_*(T_-1)));
        out[4097] = g_S2 / (float)(B_*T_);
        out[4098] = g_SA / (float)(B_*S_);
        out[4099] = tot  / (float)(B_*O_);
    }
}

extern "C" void kernel_launch(void* const* d_in, const int* in_sizes, int n_in,
                              void* d_out, int out_size)
{
    const float* x     = (const float*)d_in[0];
    const float* A     = (const float*)d_in[1];
    const float* Bm    = (const float*)d_in[2];
    const float* C     = (const float*)d_in[3];
    const float* D     = (const float*)d_in[4];
    const float* Wsel  = (const float*)d_in[5];
    const float* bsel  = (const float*)d_in[6];
    const float* gamma = (const float*)d_in[7];
    const float* beta  = (const float*)d_in[8];
    float* out = (float*)d_out;

    zeroK<<<16, 256>>>();
    cudaFuncSetAttribute(megaK, cudaFuncAttributeMaxDynamicSharedMemorySize, DSMEM);
    megaK<<<B_ + NWORK, 256, DSMEM>>>(x, Wsel, bsel, Bm, A, gamma, beta, C, D, out);
    selFin<<<B_, 128>>>(Wsel, bsel);
    finK<<<1, 256>>>(out);
}